// round 3
// baseline (speedup 1.0000x reference)
#include <cuda_runtime.h>

// GRU4Rec user module: ragged GRU(128) -> dense(128) -> L2 normalize.
// Inputs (metadata order):
//   d_in[0] x        float32 [T, 128]
//   d_in[1] offset   int32 or int64 [B]  (dtype auto-detected at runtime)
//   d_in[2] W_ih     float32 [384, 128]
//   d_in[3] W_hh     float32 [384, 128]
//   d_in[4] W_dense  float32 [128, 128]
//   d_in[5] b_dense  float32 [128]
// Output: float32 [B, 128]

#define DIMD 128
#define DIMH 128
#define G3   384
#define MAXB 2048
#define MAXLEN 200

// scratch for x_proj: 2048 * 200 * 384 floats (static device array)
__device__ float g_xproj[(size_t)MAXB * MAXLEN * G3];
// normalized int32 offsets (filled by k_off regardless of input dtype)
__device__ int g_off[MAXB];

__device__ __forceinline__ void ffma2(unsigned long long &acc,
                                      unsigned long long a,
                                      unsigned long long b) {
    asm("fma.rn.f32x2 %0, %1, %2, %0;" : "+l"(acc) : "l"(a), "l"(b));
}
__device__ __forceinline__ float f2lo(unsigned long long v) {
    return __uint_as_float((unsigned int)v);
}
__device__ __forceinline__ float f2hi(unsigned long long v) {
    return __uint_as_float((unsigned int)(v >> 32));
}

// ---------------------------------------------------------------------------
// K0: normalize offsets to int32, auto-detecting dtype.
// Valid int32 offsets: off[0]=0, off[1]>=1 (lengths >= 1).
// int64 read as int32 pairs: raw32[1] == high word of offset[0] == 0.
// ---------------------------------------------------------------------------
__global__ void k_off(const void* __restrict__ off_raw, int B) {
    const int i = blockIdx.x * blockDim.x + threadIdx.x;
    if (i >= B) return;
    const int* r32 = (const int*)off_raw;
    bool is64 = (B > 1) && (r32[1] == 0);
    int v = is64 ? (int)((const long long*)off_raw)[i] : r32[i];
    g_off[i] = v;
}

// ---------------------------------------------------------------------------
// K1: x_proj = x @ W_ih^T   ([T,128] x [128,384] -> [T,384])
// 384 threads; thread g holds W_ih row g (128 floats = 64 packed pairs) in regs.
// ---------------------------------------------------------------------------
__global__ __launch_bounds__(384, 1)
void k_xproj(const float* __restrict__ x,
             const float* __restrict__ W_ih,
             int T, int chunk) {
    const int g = threadIdx.x;

    int t0 = blockIdx.x * chunk;
    int t1 = min(T, t0 + chunk);
    if (t0 >= t1) return;  // uniform across block

    unsigned long long Wr[64];
    {
        const unsigned long long* Wp =
            (const unsigned long long*)(W_ih + (size_t)g * DIMD);
        #pragma unroll
        for (int j = 0; j < 64; j++) Wr[j] = Wp[j];
    }

    __shared__ __align__(16) float sx[2][DIMD];

    if (g < 32)
        ((float4*)sx[0])[g] = ((const float4*)x)[(size_t)t0 * 32 + g];
    __syncthreads();

    int buf = 0;
    for (int t = t0; t < t1; t++) {
        if (g < 32 && t + 1 < t1)
            ((float4*)sx[buf ^ 1])[g] = ((const float4*)x)[(size_t)(t + 1) * 32 + g];

        unsigned long long a0 = 0ull, a1 = 0ull;
        const ulonglong2* hp = (const ulonglong2*)sx[buf];
        #pragma unroll
        for (int j = 0; j < 32; j++) {
            ulonglong2 hv = hp[j];
            ffma2(a0, Wr[2 * j],     hv.x);
            ffma2(a1, Wr[2 * j + 1], hv.y);
        }
        float s = (f2lo(a0) + f2hi(a0)) + (f2lo(a1) + f2hi(a1));
        g_xproj[(size_t)t * G3 + g] = s;   // coalesced across g

        __syncthreads();
        buf ^= 1;
    }
}

// ---------------------------------------------------------------------------
// K2: per-sequence GRU recurrence + dense + L2 normalize.
// One block per sequence, 384 threads. Thread g owns W_hh row g in registers.
// ---------------------------------------------------------------------------
__global__ __launch_bounds__(384, 1)
void k_rec(const float* __restrict__ W_hh,
           const float* __restrict__ W_dense,
           const float* __restrict__ b_dense,
           float* __restrict__ out,
           int T, int B) {
    const int seq = blockIdx.x;
    const int g = threadIdx.x;

    int o  = g_off[seq];
    int oe = (seq + 1 < B) ? g_off[seq + 1] : T;
    int len = oe - o;
    // defensive clamp: never escape the scratch buffer
    if (o < 0) o = 0;
    if (len < 0) len = 0;
    if (len > MAXLEN) len = MAXLEN;

    unsigned long long Wr[64];
    {
        const unsigned long long* Wp =
            (const unsigned long long*)(W_hh + (size_t)g * DIMH);
        #pragma unroll
        for (int j = 0; j < 64; j++) Wr[j] = Wp[j];
    }

    __shared__ __align__(16) float sh_h[DIMH];
    __shared__ float sh_pre[G3];
    __shared__ float sh_xgn[DIMH];
    __shared__ float sred[4];

    if (g < DIMH) sh_h[g] = 0.0f;
    __syncthreads();

    const float* xg = g_xproj + (size_t)o * G3 + g;

    for (int t = 0; t < len; t++) {
        float xv = xg[(size_t)t * G3];   // coalesced; issued early, consumed late

        unsigned long long a0 = 0ull, a1 = 0ull;
        const ulonglong2* hp = (const ulonglong2*)sh_h;
        #pragma unroll
        for (int j = 0; j < 32; j++) {
            ulonglong2 hv = hp[j];       // broadcast LDS.128
            ffma2(a0, Wr[2 * j],     hv.x);
            ffma2(a1, Wr[2 * j + 1], hv.y);
        }
        float hg = (f2lo(a0) + f2hi(a0)) + (f2lo(a1) + f2hi(a1));

        if (g < 2 * DIMH) {
            sh_pre[g] = hg + xv;         // r, z pre-activations (xg + hg)
        } else {
            sh_pre[g] = hg;              // n: keep hg separate (r scales hg only)
            sh_xgn[g - 2 * DIMH] = xv;
        }
        __syncthreads();

        if (g < DIMH) {
            float r = __frcp_rn(1.0f + __expf(-sh_pre[g]));
            float z = __frcp_rn(1.0f + __expf(-sh_pre[DIMH + g]));
            float n = tanhf(fmaf(r, sh_pre[2 * DIMH + g], sh_xgn[g]));
            float h_old = sh_h[g];
            sh_h[g] = fmaf(z, h_old - n, n);   // (1-z)*n + z*h
        }
        __syncthreads();
    }

    // dense projection: val[d] = dot(W_dense[d], h) + b[d]   (threads 0..127)
    float val = 0.0f;
    if (g < DIMD) {
        unsigned long long a0 = 0ull, a1 = 0ull;
        const unsigned long long* Wd =
            (const unsigned long long*)(W_dense + (size_t)g * DIMH);
        const ulonglong2* hp = (const ulonglong2*)sh_h;
        #pragma unroll
        for (int j = 0; j < 32; j++) {
            ulonglong2 hv = hp[j];
            ffma2(a0, Wd[2 * j],     hv.x);
            ffma2(a1, Wd[2 * j + 1], hv.y);
        }
        val = (f2lo(a0) + f2hi(a0)) + (f2lo(a1) + f2hi(a1)) + b_dense[g];

        float ss = val * val;
        #pragma unroll
        for (int s = 16; s > 0; s >>= 1)
            ss += __shfl_xor_sync(0xffffffffu, ss, s);
        if ((g & 31) == 0) sred[g >> 5] = ss;
    }
    __syncthreads();

    if (g < DIMD) {
        float ss = sred[0] + sred[1] + sred[2] + sred[3];
        float nrm = fmaxf(sqrtf(ss), 1e-12f);
        out[(size_t)seq * DIMD + g] = val / nrm;
    }
}

// ---------------------------------------------------------------------------
extern "C" void kernel_launch(void* const* d_in, const int* in_sizes, int n_in,
                              void* d_out, int out_size) {
    const float* x       = (const float*)d_in[0];
    const void*  off     = d_in[1];                   // int32 or int64
    const float* W_ih    = (const float*)d_in[2];
    const float* W_hh    = (const float*)d_in[3];
    const float* W_dense = (const float*)d_in[4];
    const float* b_dense = (const float*)d_in[5];
    float*       out     = (float*)d_out;

    const int T = in_sizes[0] / DIMD;   // total tokens
    const int B = out_size / DIMD;      // number of sequences (robust to dtype)

    k_off<<<(B + 255) / 256, 256>>>(off, B);

    const int G1 = 1184;                // 8 waves at 1 block/SM on 148 SMs
    const int chunk = (T + G1 - 1) / G1;

    k_xproj<<<G1, 384>>>(x, W_ih, T, chunk);
    k_rec<<<B, 384>>>(W_hh, W_dense, b_dense, out, T, B);
}

// round 5
// speedup vs baseline: 1.0929x; 1.0929x over previous
#include <cuda_runtime.h>

// GRU4Rec user module: ragged GRU(128) -> dense(128) -> L2 normalize.
// Inputs (metadata order):
//   d_in[0] x        float32 [T, 128]
//   d_in[1] offset   int32 (observed; int64 auto-detected) [B]
//   d_in[2] W_ih     float32 [384, 128]
//   d_in[3] W_hh     float32 [384, 128]
//   d_in[4] W_dense  float32 [128, 128]
//   d_in[5] b_dense  float32 [128]
// Output: float32 [B, 128]
//
// R5 = resubmission of R4 (infra flake; kernel never executed):
//  - xv prefetched one full step ahead (covers L2 latency across the barrier)
//  - fast_tanh/fast_sigmoid via __expf (short serial gate phase)
//  - k_off folded into k_rec prologue (2 launches/call -> ncu lands on k_rec)

#define DIMD 128
#define DIMH 128
#define G3   384
#define MAXB 2048
#define MAXLEN 200

// scratch for x_proj: 2048 * 200 * 384 floats (static device array)
__device__ float g_xproj[(size_t)MAXB * MAXLEN * G3];

__device__ __forceinline__ void ffma2(unsigned long long &acc,
                                      unsigned long long a,
                                      unsigned long long b) {
    asm("fma.rn.f32x2 %0, %1, %2, %0;" : "+l"(acc) : "l"(a), "l"(b));
}
__device__ __forceinline__ float f2lo(unsigned long long v) {
    return __uint_as_float((unsigned int)v);
}
__device__ __forceinline__ float f2hi(unsigned long long v) {
    return __uint_as_float((unsigned int)(v >> 32));
}

// cheap accurate tanh: sign(v) * (1 - e^{-2|v|}) / (1 + e^{-2|v|})
__device__ __forceinline__ float fast_tanh(float v) {
    float av = fabsf(v);
    float e = __expf(-2.0f * av);
    float m = (1.0f - e) * __frcp_rn(1.0f + e);
    return copysignf(m, v);
}

__device__ __forceinline__ float fast_sigmoid(float v) {
    return __frcp_rn(1.0f + __expf(-v));
}

// offset dtype auto-detect: valid int32 offsets have off[1] >= 1 (lengths >= 1);
// int64 read as int32 pairs has raw32[1] == 0 (high word of offset[0]).
__device__ __forceinline__ int load_off(const void* p, int i, bool is64) {
    return is64 ? (int)((const long long*)p)[i] : ((const int*)p)[i];
}

// ---------------------------------------------------------------------------
// K1: x_proj = x @ W_ih^T   ([T,128] x [128,384] -> [T,384])
// 384 threads; thread g holds W_ih row g (128 floats = 64 packed pairs) in regs.
// ---------------------------------------------------------------------------
__global__ __launch_bounds__(384, 1)
void k_xproj(const float* __restrict__ x,
             const float* __restrict__ W_ih,
             int T, int chunk) {
    const int g = threadIdx.x;

    int t0 = blockIdx.x * chunk;
    int t1 = min(T, t0 + chunk);
    if (t0 >= t1) return;  // uniform across block

    unsigned long long Wr[64];
    {
        const unsigned long long* Wp =
            (const unsigned long long*)(W_ih + (size_t)g * DIMD);
        #pragma unroll
        for (int j = 0; j < 64; j++) Wr[j] = Wp[j];
    }

    __shared__ __align__(16) float sx[2][DIMD];

    if (g < 32)
        ((float4*)sx[0])[g] = ((const float4*)x)[(size_t)t0 * 32 + g];
    __syncthreads();

    int buf = 0;
    for (int t = t0; t < t1; t++) {
        if (g < 32 && t + 1 < t1)
            ((float4*)sx[buf ^ 1])[g] = ((const float4*)x)[(size_t)(t + 1) * 32 + g];

        unsigned long long a0 = 0ull, a1 = 0ull;
        const ulonglong2* hp = (const ulonglong2*)sx[buf];
        #pragma unroll
        for (int j = 0; j < 32; j++) {
            ulonglong2 hv = hp[j];
            ffma2(a0, Wr[2 * j],     hv.x);
            ffma2(a1, Wr[2 * j + 1], hv.y);
        }
        float s = (f2lo(a0) + f2hi(a0)) + (f2lo(a1) + f2hi(a1));
        g_xproj[(size_t)t * G3 + g] = s;   // coalesced across g

        __syncthreads();
        buf ^= 1;
    }
}

// ---------------------------------------------------------------------------
// K2: per-sequence GRU recurrence + dense + L2 normalize.
// One block per sequence, 384 threads. Thread g owns W_hh row g in registers.
// ---------------------------------------------------------------------------
__global__ __launch_bounds__(384, 1)
void k_rec(const void* __restrict__ off_raw,
           const float* __restrict__ W_hh,
           const float* __restrict__ W_dense,
           const float* __restrict__ b_dense,
           float* __restrict__ out,
           int T, int B) {
    const int seq = blockIdx.x;
    const int g = threadIdx.x;

    const bool is64 = (B > 1) && (((const int*)off_raw)[1] == 0);
    int o  = load_off(off_raw, seq, is64);
    int oe = (seq + 1 < B) ? load_off(off_raw, seq + 1, is64) : T;
    int len = oe - o;
    // defensive clamp: never escape the scratch buffer
    if (o < 0) o = 0;
    if (len < 0) len = 0;
    if (len > MAXLEN) len = MAXLEN;

    unsigned long long Wr[64];
    {
        const unsigned long long* Wp =
            (const unsigned long long*)(W_hh + (size_t)g * DIMH);
        #pragma unroll
        for (int j = 0; j < 64; j++) Wr[j] = Wp[j];
    }

    __shared__ __align__(16) float sh_h[DIMH];
    __shared__ float sh_pre[G3];
    __shared__ float sh_xgn[DIMH];
    __shared__ float sred[4];

    if (g < DIMH) sh_h[g] = 0.0f;
    __syncthreads();

    const float* xg = g_xproj + (size_t)o * G3 + g;

    // prefetch step 0's x-projection
    float xv = (len > 0) ? xg[0] : 0.0f;

    for (int t = 0; t < len; t++) {
        // prefetch next step's value: LDG issued ~1 full step before use
        float xv_next = (t + 1 < len) ? xg[(size_t)(t + 1) * G3] : 0.0f;

        unsigned long long a0 = 0ull, a1 = 0ull;
        const ulonglong2* hp = (const ulonglong2*)sh_h;
        #pragma unroll
        for (int j = 0; j < 32; j++) {
            ulonglong2 hv = hp[j];       // broadcast LDS.128
            ffma2(a0, Wr[2 * j],     hv.x);
            ffma2(a1, Wr[2 * j + 1], hv.y);
        }
        float hg = (f2lo(a0) + f2hi(a0)) + (f2lo(a1) + f2hi(a1));

        if (g < 2 * DIMH) {
            sh_pre[g] = hg + xv;         // r, z pre-activations (xg + hg)
        } else {
            sh_pre[g] = hg;              // n: keep hg separate (r scales hg only)
            sh_xgn[g - 2 * DIMH] = xv;
        }
        __syncthreads();

        if (g < DIMH) {
            float r = fast_sigmoid(sh_pre[g]);
            float z = fast_sigmoid(sh_pre[DIMH + g]);
            float n = fast_tanh(fmaf(r, sh_pre[2 * DIMH + g], sh_xgn[g]));
            float h_old = sh_h[g];
            sh_h[g] = fmaf(z, h_old - n, n);   // (1-z)*n + z*h
        }
        __syncthreads();

        xv = xv_next;
    }

    // dense projection: val[d] = dot(W_dense[d], h) + b[d]   (threads 0..127)
    float val = 0.0f;
    if (g < DIMD) {
        unsigned long long a0 = 0ull, a1 = 0ull;
        const unsigned long long* Wd =
            (const unsigned long long*)(W_dense + (size_t)g * DIMH);
        const ulonglong2* hp = (const ulonglong2*)sh_h;
        #pragma unroll
        for (int j = 0; j < 32; j++) {
            ulonglong2 hv = hp[j];
            ffma2(a0, Wd[2 * j],     hv.x);
            ffma2(a1, Wd[2 * j + 1], hv.y);
        }
        val = (f2lo(a0) + f2hi(a0)) + (f2lo(a1) + f2hi(a1)) + b_dense[g];

        float ss = val * val;
        #pragma unroll
        for (int s = 16; s > 0; s >>= 1)
            ss += __shfl_xor_sync(0xffffffffu, ss, s);
        if ((g & 31) == 0) sred[g >> 5] = ss;
    }
    __syncthreads();

    if (g < DIMD) {
        float ss = sred[0] + sred[1] + sred[2] + sred[3];
        float nrm = fmaxf(sqrtf(ss), 1e-12f);
        out[(size_t)seq * DIMD + g] = val / nrm;
    }
}

// ---------------------------------------------------------------------------
extern "C" void kernel_launch(void* const* d_in, const int* in_sizes, int n_in,
                              void* d_out, int out_size) {
    const float* x       = (const float*)d_in[0];
    const void*  off     = d_in[1];                   // int32 or int64
    const float* W_ih    = (const float*)d_in[2];
    const float* W_hh    = (const float*)d_in[3];
    const float* W_dense = (const float*)d_in[4];
    const float* b_dense = (const float*)d_in[5];
    float*       out     = (float*)d_out;

    const int T = in_sizes[0] / DIMD;   // total tokens
    const int B = out_size / DIMD;      // number of sequences

    const int G1 = 1184;                // 8 waves at 1 block/SM on 148 SMs
    const int chunk = (T + G1 - 1) / G1;

    k_xproj<<<G1, 384>>>(x, W_ih, T, chunk);
    k_rec<<<B, 384>>>(off, W_hh, W_dense, b_dense, out, T, B);
}

// round 7
// speedup vs baseline: 1.3965x; 1.2778x over previous
#include <cuda_runtime.h>

// GRU4Rec user module: ragged GRU(128) -> dense(128) -> L2 normalize.
// Inputs: x f32[T,128], offset i32[B] (i64 auto-detect), W_ih f32[384,128],
//         W_hh f32[384,128], W_dense f32[128,128], b_dense f32[128]
// Output: f32[B,128]
//
// R7 = resubmission of R6 (infra flake; never executed).
// Design per R5 ncu evidence (occ 18.7%, issue 24%, L1 59.7%):
//  - k_rec: 2 length-sorted sequences per block (counting-sort prepass)
//  - k_xproj: 4-token tiles, 1 barrier per tile, 8 indep FMA chains

#define DIMD 128
#define DIMH 128
#define G3   384
#define MAXB 4096
#define MAXLEN 200

__device__ float g_xproj[(size_t)2048 * MAXLEN * G3];
__device__ int g_off[MAXB];
__device__ int g_len[MAXB];
__device__ int g_order[MAXB];

__device__ __forceinline__ void ffma2(unsigned long long &acc,
                                      unsigned long long a,
                                      unsigned long long b) {
    asm("fma.rn.f32x2 %0, %1, %2, %0;" : "+l"(acc) : "l"(a), "l"(b));
}
__device__ __forceinline__ float f2lo(unsigned long long v) {
    return __uint_as_float((unsigned int)v);
}
__device__ __forceinline__ float f2hi(unsigned long long v) {
    return __uint_as_float((unsigned int)(v >> 32));
}
__device__ __forceinline__ float fast_tanh(float v) {
    float av = fabsf(v);
    float e = __expf(-2.0f * av);
    float m = (1.0f - e) * __frcp_rn(1.0f + e);
    return copysignf(m, v);
}
__device__ __forceinline__ float fast_sigmoid(float v) {
    return __frcp_rn(1.0f + __expf(-v));
}
__device__ __forceinline__ int load_off(const void* p, int i, bool is64) {
    return is64 ? (int)((const long long*)p)[i] : ((const int*)p)[i];
}

// ---------------------------------------------------------------------------
// K0: offsets/lengths + counting sort of sequence indices by length.
// Per-sequence results are bit-exact regardless of atomic ordering.
// ---------------------------------------------------------------------------
__global__ void k_sort(const void* __restrict__ off_raw, int T, int B) {
    __shared__ int s_cnt[MAXLEN + 1];
    const int tid = threadIdx.x;
    const bool is64 = (B > 1) && (((const int*)off_raw)[1] == 0);

    for (int i = tid; i <= MAXLEN; i += blockDim.x) s_cnt[i] = 0;
    __syncthreads();

    for (int i = tid; i < B; i += blockDim.x) {
        int o  = load_off(off_raw, i, is64);
        int oe = (i + 1 < B) ? load_off(off_raw, i + 1, is64) : T;
        int l = oe - o;
        if (o < 0) o = 0;
        if (l < 0) l = 0;
        if (l > MAXLEN) l = MAXLEN;
        g_off[i] = o;
        g_len[i] = l;
        atomicAdd(&s_cnt[l], 1);
    }
    __syncthreads();

    if (tid == 0) {
        int run = 0;
        for (int j = 0; j <= MAXLEN; j++) { int c = s_cnt[j]; s_cnt[j] = run; run += c; }
    }
    __syncthreads();

    for (int i = tid; i < B; i += blockDim.x) {
        int pos = atomicAdd(&s_cnt[g_len[i]], 1);
        g_order[pos] = i;
    }
}

// ---------------------------------------------------------------------------
// K1: x_proj = x @ W_ih^T. 4-token tiles, double-buffered, 1 barrier/tile.
// ---------------------------------------------------------------------------
__global__ __launch_bounds__(384, 1)
void k_xproj(const float* __restrict__ x,
             const float* __restrict__ W_ih,
             int T, int chunk) {
    const int g = threadIdx.x;

    int t0 = blockIdx.x * chunk;
    int t1 = min(T, t0 + chunk);
    if (t0 >= t1) return;  // uniform across block

    unsigned long long Wr[64];
    {
        const unsigned long long* Wp =
            (const unsigned long long*)(W_ih + (size_t)g * DIMD);
        #pragma unroll
        for (int j = 0; j < 64; j++) Wr[j] = Wp[j];
    }

    __shared__ __align__(16) float sx[2][4][DIMD];

    // prologue: load tile 0 (threads 0..127: token g/32, float4 g%32)
    if (g < 128) {
        int tk = t0 + (g >> 5);
        if (tk < t1)
            ((float4*)sx[0][g >> 5])[g & 31] = ((const float4*)x)[(size_t)tk * 32 + (g & 31)];
    }
    __syncthreads();

    int buf = 0;
    for (int ts = t0; ts < t1; ts += 4) {
        // prefetch next tile into other buffer (its last reader finished
        // before the barrier that ended the previous iteration)
        if (g < 128) {
            int tk = ts + 4 + (g >> 5);
            if (tk < t1)
                ((float4*)sx[buf ^ 1][g >> 5])[g & 31] =
                    ((const float4*)x)[(size_t)tk * 32 + (g & 31)];
        }

        unsigned long long a0[4], a1[4];
        #pragma unroll
        for (int k = 0; k < 4; k++) { a0[k] = 0ull; a1[k] = 0ull; }

        const ulonglong2* hp0 = (const ulonglong2*)sx[buf][0];
        const ulonglong2* hp1 = (const ulonglong2*)sx[buf][1];
        const ulonglong2* hp2 = (const ulonglong2*)sx[buf][2];
        const ulonglong2* hp3 = (const ulonglong2*)sx[buf][3];
        #pragma unroll
        for (int j = 0; j < 32; j++) {
            ulonglong2 v0 = hp0[j], v1 = hp1[j], v2 = hp2[j], v3 = hp3[j];
            ffma2(a0[0], Wr[2 * j], v0.x);  ffma2(a1[0], Wr[2 * j + 1], v0.y);
            ffma2(a0[1], Wr[2 * j], v1.x);  ffma2(a1[1], Wr[2 * j + 1], v1.y);
            ffma2(a0[2], Wr[2 * j], v2.x);  ffma2(a1[2], Wr[2 * j + 1], v2.y);
            ffma2(a0[3], Wr[2 * j], v3.x);  ffma2(a1[3], Wr[2 * j + 1], v3.y);
        }
        #pragma unroll
        for (int k = 0; k < 4; k++) {
            int tk = ts + k;
            if (tk < t1) {
                float s = (f2lo(a0[k]) + f2hi(a0[k])) + (f2lo(a1[k]) + f2hi(a1[k]));
                g_xproj[(size_t)tk * G3 + g] = s;
            }
        }

        __syncthreads();
        buf ^= 1;
    }
}

// ---------------------------------------------------------------------------
// K2: GRU recurrence, 2 length-sorted sequences per block (384 threads).
// Thread g owns W_hh row g; both sequences share the weight registers.
// ---------------------------------------------------------------------------
__global__ __launch_bounds__(384, 1)
void k_rec(const float* __restrict__ W_hh,
           const float* __restrict__ W_dense,
           const float* __restrict__ b_dense,
           float* __restrict__ out,
           int B) {
    const int g = threadIdx.x;

    const int i0 = 2 * blockIdx.x;
    const int i1 = i0 + 1;
    const int seq0 = g_order[i0];
    const int seq1 = (i1 < B) ? g_order[i1] : -1;

    const int o0 = g_off[seq0];
    const int len0 = g_len[seq0];
    const int o1 = (seq1 >= 0) ? g_off[seq1] : 0;
    const int len1 = (seq1 >= 0) ? g_len[seq1] : 0;
    const int lmax = max(len0, len1);

    unsigned long long Wr[64];
    {
        const unsigned long long* Wp =
            (const unsigned long long*)(W_hh + (size_t)g * DIMH);
        #pragma unroll
        for (int j = 0; j < 64; j++) Wr[j] = Wp[j];
    }

    __shared__ __align__(16) float sh_h[2][DIMH];
    __shared__ float sh_pre[2][G3];
    __shared__ float sh_xgn[2][DIMH];
    __shared__ float sred[8];

    if (g < DIMH) { sh_h[0][g] = 0.0f; sh_h[1][g] = 0.0f; }
    __syncthreads();

    const float* xg0 = g_xproj + (size_t)o0 * G3 + g;
    const float* xg1 = g_xproj + (size_t)o1 * G3 + g;

    float xv0 = (0 < len0) ? xg0[0] : 0.0f;
    float xv1 = (0 < len1) ? xg1[0] : 0.0f;

    for (int t = 0; t < lmax; t++) {
        float xn0 = (t + 1 < len0) ? xg0[(size_t)(t + 1) * G3] : 0.0f;
        float xn1 = (t + 1 < len1) ? xg1[(size_t)(t + 1) * G3] : 0.0f;

        unsigned long long a00 = 0ull, a01 = 0ull, a10 = 0ull, a11 = 0ull;
        const ulonglong2* hp0 = (const ulonglong2*)sh_h[0];
        const ulonglong2* hp1 = (const ulonglong2*)sh_h[1];
        #pragma unroll
        for (int j = 0; j < 32; j++) {
            ulonglong2 v0 = hp0[j];            // broadcast LDS.128
            ulonglong2 v1 = hp1[j];
            ffma2(a00, Wr[2 * j],     v0.x);
            ffma2(a01, Wr[2 * j + 1], v0.y);
            ffma2(a10, Wr[2 * j],     v1.x);
            ffma2(a11, Wr[2 * j + 1], v1.y);
        }
        float hg0 = (f2lo(a00) + f2hi(a00)) + (f2lo(a01) + f2hi(a01));
        float hg1 = (f2lo(a10) + f2hi(a10)) + (f2lo(a11) + f2hi(a11));

        if (g < 2 * DIMH) {
            sh_pre[0][g] = hg0 + xv0;          // r,z pre-activations
            sh_pre[1][g] = hg1 + xv1;
        } else {
            sh_pre[0][g] = hg0;                // n: hg kept separate
            sh_pre[1][g] = hg1;
            sh_xgn[0][g - 2 * DIMH] = xv0;
            sh_xgn[1][g - 2 * DIMH] = xv1;
        }
        __syncthreads();

        if (g < 2 * DIMH) {                    // warps 0..7: gate math, 2 seqs
            int s = g >> 7;                    // uniform per warp
            int j = g & (DIMH - 1);
            int ls = s ? len1 : len0;
            if (t < ls) {
                float r = fast_sigmoid(sh_pre[s][j]);
                float z = fast_sigmoid(sh_pre[s][DIMH + j]);
                float n = fast_tanh(fmaf(r, sh_pre[s][2 * DIMH + j], sh_xgn[s][j]));
                float h_old = sh_h[s][j];
                sh_h[s][j] = fmaf(z, h_old - n, n);
            }
        }
        __syncthreads();

        xv0 = xn0; xv1 = xn1;
    }

    // dense + L2 normalize: threads 0..255 (s = g>>7, d = g&127)
    float val = 0.0f;
    const int s = g >> 7;
    const int d = g & (DIMH - 1);
    if (g < 2 * DIMH) {
        unsigned long long a0 = 0ull, a1 = 0ull;
        const unsigned long long* Wd =
            (const unsigned long long*)(W_dense + (size_t)d * DIMH);
        const ulonglong2* hp = (const ulonglong2*)sh_h[s];
        #pragma unroll
        for (int j = 0; j < 32; j++) {
            ulonglong2 hv = hp[j];
            ffma2(a0, Wd[2 * j],     hv.x);
            ffma2(a1, Wd[2 * j + 1], hv.y);
        }
        val = (f2lo(a0) + f2hi(a0)) + (f2lo(a1) + f2hi(a1)) + b_dense[d];

        float ss = val * val;
        #pragma unroll
        for (int sh = 16; sh > 0; sh >>= 1)
            ss += __shfl_xor_sync(0xffffffffu, ss, sh);
        if ((g & 31) == 0) sred[g >> 5] = ss;   // warps 0..7
    }
    __syncthreads();

    if (g < 2 * DIMH) {
        int base = s * 4;
        float ss = sred[base] + sred[base + 1] + sred[base + 2] + sred[base + 3];
        float nrm = fmaxf(sqrtf(ss), 1e-12f);
        int seq = s ? seq1 : seq0;
        if (seq >= 0)
            out[(size_t)seq * DIMD + d] = val / nrm;
    }
}

// ---------------------------------------------------------------------------
extern "C" void kernel_launch(void* const* d_in, const int* in_sizes, int n_in,
                              void* d_out, int out_size) {
    const float* x       = (const float*)d_in[0];
    const void*  off     = d_in[1];                   // int32 or int64
    const float* W_ih    = (const float*)d_in[2];
    const float* W_hh    = (const float*)d_in[3];
    const float* W_dense = (const float*)d_in[4];
    const float* b_dense = (const float*)d_in[5];
    float*       out     = (float*)d_out;

    const int T = in_sizes[0] / DIMD;   // total tokens
    const int B = out_size / DIMD;      // number of sequences

    k_sort<<<1, 256>>>(off, T, B);

    const int G1 = 1184;                // 8 waves at 1 block/SM on 148 SMs
    const int chunk = (T + G1 - 1) / G1;
    k_xproj<<<G1, 384>>>(x, W_ih, T, chunk);

    const int G2 = (B + 1) / 2;
    k_rec<<<G2, 384>>>(W_hh, W_dense, b_dense, out, B);
}